// round 13
// baseline (speedup 1.0000x reference)
#include <cuda_runtime.h>

// Fixed shapes: n=2, c=64, s=4, h=64, w=44
#define N_  2
#define C_  64
#define S_  4
#define H_  64
#define W_  44
#define B_  (N_ * S_)            // 8 effective batches
#define P_  (H_ * W_)            // 2816 pixels
#define R_  3
#define KT  49

#define TH  4                    // tile rows per block
#define CC  8                    // channels staged per chunk
#define NCH (C_ / CC)            // 8 chunks
#define QS  11                   // pixel-quads per image row (44/4)
#define L16 16                   // lanes per quad (8 rows x 2 halves)
#define HALO_H (TH + 2 * R_)     // 10 shared rows
#define SW  52                   // stored row stride: 4 left pad + 44 + 4 right pad
#define NTHREADS (QS * TH * L16) // 704

#define NF1 5                    // f1 elems staged per thread per chunk (8*10*44/704)
#define NF0 2                    // f0 elems staged per thread per chunk
#define CHSTRIDE (S_ * P_)       // per-channel element stride
#define F1PLANE (HALO_H * SW)    // 520 floats per channel plane (130 float4)
#define F0PLANE (TH * W_)        // 176 floats per channel plane (44 float4)

__global__ __launch_bounds__(NTHREADS, 1)
void corr_flow_kernel(const float* __restrict__ f0g,
                      const float* __restrict__ f1g,
                      float* __restrict__ out) {
    __shared__ __align__(16) float f1s[2][CC][HALO_H][SW];  // 33280 B
    __shared__ __align__(16) float f0s[2][CC][TH][W_];      // 11264 B

    const int tid = threadIdx.x;
    const int l16 = tid & 15;            // lane within quad-group
    const int qid = tid >> 4;            // quad slot 0..43
    const int q   = qid % QS;            // quad x index 0..10
    const int ty  = qid / QS;            // tile row 0..3
    const int r   = l16 >> 1;            // window row 0..7 (7 = dup of 6, masked)
    const int h   = l16 & 1;             // tap half: dx = 4h + i - 3
    const bool rv = (r < 7);
    const int rr  = rv ? r : 6;          // clamped row actually read

    const int blk   = blockIdx.x;        // 0..127
    const int b     = blk >> 4;
    const int ytile = blk & 15;
    const int y0    = ytile * TH;
    const int n_idx = b / S_;
    const int s_idx = b - n_idx * S_;

    const int base = (n_idx * C_ * S_ + s_idx) * P_;

    // ---- precompute staging maps (chunk-invariant) ----
    int f1_s[NF1];
    int f1_g[NF1];
#pragma unroll
    for (int k = 0; k < NF1; k++) {
        int i   = tid + k * NTHREADS;
        int cc  = i / (HALO_H * W_);
        int rem = i - cc * (HALO_H * W_);
        int rs  = rem / W_;
        int x   = rem - rs * W_;
        int gy  = y0 - R_ + rs;
        f1_s[k] = cc * F1PLANE + rs * SW + x + 4;   // +4: left pad
        f1_g[k] = (gy >= 0 && gy < H_) ? (base + cc * CHSTRIDE + gy * W_ + x) : -1;
    }
    int f0_s[NF0];
    int f0_g[NF0];
#pragma unroll
    for (int k = 0; k < NF0; k++) {
        int i   = tid + k * NTHREADS;
        int cc  = i / (TH * W_);
        int rem = i - cc * (TH * W_);
        int rs  = rem / W_;
        int x   = rem - rs * W_;
        f0_s[k] = i;
        f0_g[k] = base + cc * CHSTRIDE + (y0 + rs) * W_ + x;
    }

    // 16 accumulators: acc[j*4+i] = pixel (4q+j), tap dx = 4h+i-3
    float acc[16];
#pragma unroll
    for (int i = 0; i < 16; i++) acc[i] = 0.f;

    // zero both f1 buffers once (pads & out-of-image rows stay zero)
    {
        float* zp = &f1s[0][0][0][0];
        for (int i = tid; i < 2 * CC * HALO_H * SW; i += NTHREADS) zp[i] = 0.f;
    }
    // zero-fill must be visible before chunk-0 staging (different writer threads)
    __syncthreads();

    // ---- prologue: prefetch chunk 0, store into buffer 0 ----
    float r1[NF1], r0[NF0];
#pragma unroll
    for (int k = 0; k < NF1; k++) r1[k] = (f1_g[k] >= 0) ? f1g[f1_g[k]] : 0.f;
#pragma unroll
    for (int k = 0; k < NF0; k++) r0[k] = f0g[f0_g[k]];

    float* f1b0 = &f1s[0][0][0][0];
    float* f1b1 = &f1s[1][0][0][0];
    float* f0b0 = &f0s[0][0][0][0];
    float* f0b1 = &f0s[1][0][0][0];

#pragma unroll
    for (int k = 0; k < NF1; k++) f1b0[f1_s[k]] = r1[k];
#pragma unroll
    for (int k = 0; k < NF0; k++) f0b0[f0_s[k]] = r0[k];
    __syncthreads();

    // vector-load slot offsets (float4 units), chunk-invariant parts
    const int voff  = (ty + rr) * (SW / 4) + q + h;   // f1: row (ty+rr), col 4q+4h
    const int f0off = ty * (W_ / 4) + q;              // f0: quad base

    // ---- pipelined mainloop ----
#pragma unroll 2
    for (int c = 0; c < NCH; c++) {
        if (c < NCH - 1) {
            int ch_off = (c + 1) * CC * CHSTRIDE;
#pragma unroll
            for (int k = 0; k < NF1; k++)
                r1[k] = (f1_g[k] >= 0) ? f1g[f1_g[k] + ch_off] : 0.f;
#pragma unroll
            for (int k = 0; k < NF0; k++)
                r0[k] = f0g[f0_g[k] + ch_off];
        }

        const float4* vp  = (const float4*)((c & 1) ? f1b1 : f1b0) + voff;
        const float4* f0p = (const float4*)((c & 1) ? f0b1 : f0b0) + f0off;

#pragma unroll
        for (int cc = 0; cc < CC; cc++) {
            float4 lo4 = vp[cc * (F1PLANE / 4)];       // stored cols 4q+4h .. +3
            float4 hi4 = vp[cc * (F1PLANE / 4) + 1];   // stored cols 4q+4h+4 .. +7
            float4 a4  = f0p[cc * (F0PLANE / 4)];      // 4 f0 pixels (broadcast x16)
            float v[8] = {lo4.x, lo4.y, lo4.z, lo4.w, hi4.x, hi4.y, hi4.z, hi4.w};
            float a[4] = {a4.x, a4.y, a4.z, a4.w};
#pragma unroll
            for (int j = 0; j < 4; j++) {
#pragma unroll
                for (int i = 0; i < 4; i++) {
                    // stored col of tap: 4q + (j+i+1) + 4h  ->  v[j+i+1]
                    acc[j * 4 + i] = fmaf(a[j], v[j + i + 1], acc[j * 4 + i]);
                }
            }
        }

        if (c < NCH - 1) {
            float* f1d = (c & 1) ? f1b0 : f1b1;
            float* f0d = (c & 1) ? f0b0 : f0b1;
#pragma unroll
            for (int k = 0; k < NF1; k++) f1d[f1_s[k]] = r1[k];
#pragma unroll
            for (int k = 0; k < NF0; k++) f0d[f0_s[k]] = r0[k];
            __syncthreads();
        }
    }

    // ---- epilogue: per-pixel masked softmax, reduced over the 16 quad lanes ----
    const int y   = y0 + ty;
    const int dyv = r - R_;                       // valid only when rv
    const int gy  = y + dyv;
    const bool vy = rv && (gy >= 0) && (gy < H_);
    const float scale = 0.125f;                   // 1/sqrt(64)

    float m[4];
#pragma unroll
    for (int j = 0; j < 4; j++) {
        m[j] = -1e30f;
#pragma unroll
        for (int i = 0; i < 4; i++) {
            int dx = 4 * h + i - 3;
            int gx = 4 * q + j + dx;
            bool ok = vy && (dx <= 3) && (gx >= 0) && (gx < W_);
            if (ok) m[j] = fmaxf(m[j], acc[j * 4 + i] * scale);
        }
    }
#pragma unroll
    for (int j = 0; j < 4; j++) {
        m[j] = fmaxf(m[j], __shfl_xor_sync(0xffffffffu, m[j], 1));
        m[j] = fmaxf(m[j], __shfl_xor_sync(0xffffffffu, m[j], 2));
        m[j] = fmaxf(m[j], __shfl_xor_sync(0xffffffffu, m[j], 4));
        m[j] = fmaxf(m[j], __shfl_xor_sync(0xffffffffu, m[j], 8));
    }

    float se[4], sx[4], sy[4];
#pragma unroll
    for (int j = 0; j < 4; j++) {
        se[j] = 0.f; sx[j] = 0.f; sy[j] = 0.f;
#pragma unroll
        for (int i = 0; i < 4; i++) {
            int dx = 4 * h + i - 3;
            int gx = 4 * q + j + dx;
            bool ok = vy && (dx <= 3) && (gx >= 0) && (gx < W_);
            if (ok) {
                float e = __expf(acc[j * 4 + i] * scale - m[j]);
                se[j] += e;
                sx[j] += e * (float)dx;
                sy[j] += e * (float)dyv;
            }
        }
    }
#pragma unroll
    for (int j = 0; j < 4; j++) {
        se[j] += __shfl_xor_sync(0xffffffffu, se[j], 1);
        se[j] += __shfl_xor_sync(0xffffffffu, se[j], 2);
        se[j] += __shfl_xor_sync(0xffffffffu, se[j], 4);
        se[j] += __shfl_xor_sync(0xffffffffu, se[j], 8);
        sx[j] += __shfl_xor_sync(0xffffffffu, sx[j], 1);
        sx[j] += __shfl_xor_sync(0xffffffffu, sx[j], 2);
        sx[j] += __shfl_xor_sync(0xffffffffu, sx[j], 4);
        sx[j] += __shfl_xor_sync(0xffffffffu, sx[j], 8);
        sy[j] += __shfl_xor_sync(0xffffffffu, sy[j], 1);
        sy[j] += __shfl_xor_sync(0xffffffffu, sy[j], 2);
        sy[j] += __shfl_xor_sync(0xffffffffu, sy[j], 4);
        sy[j] += __shfl_xor_sync(0xffffffffu, sy[j], 8);
    }

    if (l16 < 4) {
        int j = l16;
        int x = 4 * q + j;
        float inv = 1.0f / se[j];
        int ob = ((n_idx * 2) * S_ + s_idx) * P_ + y * W_ + x;
        out[ob]           = sx[j] * inv;   // flow x
        out[ob + S_ * P_] = sy[j] * inv;   // flow y
    }
}

extern "C" void kernel_launch(void* const* d_in, const int* in_sizes, int n_in,
                              void* d_out, int out_size) {
    const float* f0 = (const float*)d_in[0];
    const float* f1 = (const float*)d_in[1];
    float* out = (float*)d_out;
    corr_flow_kernel<<<B_ * (H_ / TH), NTHREADS>>>(f0, f1, out);
}